// round 13
// baseline (speedup 1.0000x reference)
#include <cuda_runtime.h>
#include <math.h>

#define NN 4096
#define EE 1024
#define HH 16
#define VV 32
#define LL 6
#define HV 512
#define E2 2048

typedef unsigned long long ull;

// ---------------- scratch (static device globals; no allocations) -------------
__device__ float g_z [NN * EE];
__device__ float g_q [HH * NN * VV];
__device__ float g_k [HH * NN * VV];
__device__ float g_v [HH * NN * VV];
__device__ float g_o [NN * HV];
__device__ float g_an[NN * EE];
__device__ float g_h1[NN * E2];
__device__ float g_u [NN * EE];

// ---------------- packed f32x2 helpers -----------------------------------------
__device__ __forceinline__ ull pk2(float x, float y) {
    ull u;
    asm("mov.b64 %0, {%1, %2};" : "=l"(u) : "f"(x), "f"(y));
    return u;
}
__device__ __forceinline__ void fma2(ull& c, ull a, ull b) {
    asm("fma.rn.f32x2 %0, %1, %2, %0;" : "+l"(c) : "l"(a), "l"(b));
}
__device__ __forceinline__ ull mul2(ull a, ull b) {
    ull d;
    asm("mul.rn.f32x2 %0, %1, %2;" : "=l"(d) : "l"(a), "l"(b));
    return d;
}
__device__ __forceinline__ float2 upk(ull u) {
    float x, y;
    asm("mov.b64 {%0, %1}, %2;" : "=f"(x), "=f"(y) : "l"(u));
    return make_float2(x, y);
}

// ------------------------------- embedding ------------------------------------
__global__ void embed_kernel(const int* __restrict__ ctx,
                             const float* __restrict__ table,
                             const float* __restrict__ pos) {
    int n = blockIdx.x;
    int t = threadIdx.x;
    int idx = ctx[n];
    const float4* tr = (const float4*)(table + (size_t)idx * EE);
    const float4* pr = (const float4*)(pos + (size_t)n * EE);
    float4* zr = (float4*)(g_z + (size_t)n * EE);
    float4 a = tr[t], b = pr[t];
    zr[t] = make_float4(a.x + b.x, a.y + b.y, a.z + b.z, a.w + b.w);
}

// ------------------------------- f32x2 GEMM (BM=128, BN=64) --------------------
// C[4096, NOUT] = A[4096, KTOT] @ B[KTOT, NOUT] (+bias)(+leaky)(+res).
// BK=16, 256 threads, 8x4 microtile (8 rows x 2 packed col-pairs).
// Halved BN vs R10: T_CTA halves -> finer tail granularity, same inner rate.
template <int KTOT, int NOUT, bool HAS_BIAS, bool LEAKY, bool HAS_RES, bool QKV>
__device__ __forceinline__ void gemm_x2_core(const float* __restrict__ A,
                                             const float* __restrict__ B,
                                             const float* __restrict__ bias,
                                             const float* __restrict__ res,
                                             float* __restrict__ C) {
    __shared__ float As[16][132];   // [k][m] transposed
    __shared__ float Bs[16][68];    // [k][n]

    int tid = threadIdx.x;
    int m0 = blockIdx.x * 128, n0 = blockIdx.y * 64;
    int tr = tid >> 4, tc = tid & 15;           // rows tr*8.., cols tc*4..
    int rowA = tid >> 1, colA = (tid & 1) * 8;  // A: 128 rows x 16 k
    int rowB = tid >> 4, colB = (tid & 15) * 4; // B: 16 k x 64 n

    ull acc[8][2];
#pragma unroll
    for (int i = 0; i < 8; i++) { acc[i][0] = 0ull; acc[i][1] = 0ull; }

    for (int k0 = 0; k0 < KTOT; k0 += 16) {
        float4 a0g = *(const float4*)&A[(size_t)(m0 + rowA) * KTOT + k0 + colA];
        float4 a1g = *(const float4*)&A[(size_t)(m0 + rowA) * KTOT + k0 + colA + 4];
        float4 bg;
        {
            int kk = k0 + rowB;
            if (QKV) {
                int n = n0 + colB;
                int h = n >> 5, v = n & 31;
                bg = *(const float4*)&B[((size_t)h * EE + kk) * VV + v];
            } else {
                bg = *(const float4*)&B[(size_t)kk * NOUT + n0 + colB];
            }
        }
        __syncthreads();
        As[colA + 0][rowA] = a0g.x; As[colA + 1][rowA] = a0g.y;
        As[colA + 2][rowA] = a0g.z; As[colA + 3][rowA] = a0g.w;
        As[colA + 4][rowA] = a1g.x; As[colA + 5][rowA] = a1g.y;
        As[colA + 6][rowA] = a1g.z; As[colA + 7][rowA] = a1g.w;
        *(float4*)&Bs[rowB][colB] = bg;
        __syncthreads();
#pragma unroll
        for (int kk = 0; kk < 16; kk++) {
            float4 a0 = *(const float4*)&As[kk][tr * 8];
            float4 a1 = *(const float4*)&As[kk][tr * 8 + 4];
            ull b0 = *(const ull*)&Bs[kk][tc * 4 + 0];
            ull b1 = *(const ull*)&Bs[kk][tc * 4 + 2];
            ull ap[8];
            ap[0] = pk2(a0.x, a0.x); ap[1] = pk2(a0.y, a0.y);
            ap[2] = pk2(a0.z, a0.z); ap[3] = pk2(a0.w, a0.w);
            ap[4] = pk2(a1.x, a1.x); ap[5] = pk2(a1.y, a1.y);
            ap[6] = pk2(a1.z, a1.z); ap[7] = pk2(a1.w, a1.w);
#pragma unroll
            for (int i = 0; i < 8; i++) {
                fma2(acc[i][0], ap[i], b0);
                fma2(acc[i][1], ap[i], b1);
            }
        }
    }

#pragma unroll
    for (int i = 0; i < 8; i++) {
        size_t row = (size_t)(m0 + tr * 8 + i);
        int col = n0 + tc * 4;
        float v[4];
        {
            float2 t0 = upk(acc[i][0]), t1 = upk(acc[i][1]);
            v[0] = t0.x; v[1] = t0.y; v[2] = t1.x; v[3] = t1.y;
        }
        if (HAS_BIAS) {
#pragma unroll
            for (int j = 0; j < 4; j++) v[j] += bias[col + j];
        }
        if (LEAKY) {
#pragma unroll
            for (int j = 0; j < 4; j++) v[j] = v[j] >= 0.f ? v[j] : 0.01f * v[j];
        }
        if (QKV) {
            int h = col >> 5, vv = col & 31;
            *(float4*)&C[(size_t)h * NN * VV + row * VV + vv] =
                make_float4(v[0], v[1], v[2], v[3]);
        } else {
            if (HAS_RES) {
                float4 r0 = *(const float4*)&res[row * NOUT + col];
                v[0] += r0.x; v[1] += r0.y; v[2] += r0.z; v[3] += r0.w;
            }
            *(float4*)&C[row * NOUT + col] = make_float4(v[0], v[1], v[2], v[3]);
        }
    }
}

__global__ __launch_bounds__(256, 1) void qkv_x2(const float* __restrict__ Wq,
                                                 const float* __restrict__ Wk,
                                                 const float* __restrict__ Wv,
                                                 int layer) {
    int which = blockIdx.z;
    const float* W = (which == 0 ? Wq : which == 1 ? Wk : Wv)
                     + (size_t)layer * HH * EE * VV;
    float* outp = which == 0 ? g_q : which == 1 ? g_k : g_v;
    gemm_x2_core<EE, HV, false, false, false, true>(g_z, W, nullptr, nullptr, outp);
}
__global__ __launch_bounds__(256, 1) void wo_x2(const float* __restrict__ B) {
    gemm_x2_core<HV, EE, false, false, true, false>(g_o, B, nullptr, g_z, g_u);
}
__global__ __launch_bounds__(256, 1) void ff1_x2(const float* __restrict__ B,
                                                 const float* __restrict__ bias) {
    gemm_x2_core<EE, E2, true, true, false, false>(g_an, B, bias, nullptr, g_h1);
}
__global__ __launch_bounds__(256, 1) void ff2_x2(const float* __restrict__ B,
                                                 const float* __restrict__ bias) {
    gemm_x2_core<E2, EE, true, false, true, false>(g_h1, B, bias, g_an, g_u);
}

// ------------------------------- flash attention (32 queries / CTA) ------------
// Per block: one head, 32 queries, 64-key tiles. In-register online softmax:
// thread (tr=tid>>4, tc=tid&15) owns q-rows {2tr,2tr+1}, keys 4tc..4tc+3;
// the 16 lanes sharing tr cover all 64 keys, so row max/sum reduce via
// shfl_xor(1,2,4,8). Per-row arithmetic order identical to the 64q version.
__global__ __launch_bounds__(256) void attn_kernel() {
    __shared__ float Qs[32][34];     // [d][q], pre-scaled
    __shared__ float Ks[32][68];     // [d][key]
    __shared__ float Vs[64][36];     // [key][d]
    __shared__ float Psh[64][34];    // P transposed: [key][q]
    int tid = threadIdx.x;
    int h = blockIdx.y;
    int q0 = blockIdx.x * 32;
    const float scale = 0.17677669529663687f;  // 1/sqrt(32)
    int r8 = tid >> 3;             // 0..31 (K/V loader)
    int c4 = (tid & 7) * 4;
    const float* qb = g_q + (size_t)h * NN * VV;
    const float* kb = g_k + (size_t)h * NN * VV;
    const float* vb = g_v + (size_t)h * NN * VV;
    if (tid < 128) {               // Q loader: 32 rows x 32 d
        int qr = tid >> 2;
        int qc = (tid & 3) * 8;
        float4 qa = *(const float4*)&qb[(size_t)(q0 + qr) * VV + qc];
        float4 qcv = *(const float4*)&qb[(size_t)(q0 + qr) * VV + qc + 4];
        Qs[qc + 0][qr] = qa.x * scale;  Qs[qc + 1][qr] = qa.y * scale;
        Qs[qc + 2][qr] = qa.z * scale;  Qs[qc + 3][qr] = qa.w * scale;
        Qs[qc + 4][qr] = qcv.x * scale; Qs[qc + 5][qr] = qcv.y * scale;
        Qs[qc + 6][qr] = qcv.z * scale; Qs[qc + 7][qr] = qcv.w * scale;
    }
    int tr = tid >> 4;             // q rows 2tr, 2tr+1
    int tc = tid & 15;             // keys 4tc.. (S); d-pair 2tc (PV/out)
    int sk = tc * 4;
    float m[2], l[2];
#pragma unroll
    for (int i = 0; i < 2; i++) { m[i] = -INFINITY; l[i] = 0.f; }
    ull oacc[2] = {0ull, 0ull};

    const int NT = NN / 64;
    for (int kt = 0; kt < NT; kt++) {
        int k0 = kt * 64;
        float4 ka = *(const float4*)&kb[(size_t)(k0 + r8) * VV + c4];
        float4 kc = *(const float4*)&kb[(size_t)(k0 + r8 + 32) * VV + c4];
        float4 va = *(const float4*)&vb[(size_t)(k0 + r8) * VV + c4];
        float4 vc = *(const float4*)&vb[(size_t)(k0 + r8 + 32) * VV + c4];
        __syncthreads();   // prior PV done with Vs/Psh (also orders Qs writes)
        Ks[c4 + 0][r8] = ka.x; Ks[c4 + 1][r8] = ka.y;
        Ks[c4 + 2][r8] = ka.z; Ks[c4 + 3][r8] = ka.w;
        Ks[c4 + 0][r8 + 32] = kc.x; Ks[c4 + 1][r8 + 32] = kc.y;
        Ks[c4 + 2][r8 + 32] = kc.z; Ks[c4 + 3][r8 + 32] = kc.w;
        *(float4*)&Vs[r8][c4] = va;
        *(float4*)&Vs[r8 + 32][c4] = vc;
        __syncthreads();

        // S = Q K^T : 2 query rows x 2 packed key-pairs (f32x2)
        ull sp[2][2];
        sp[0][0] = 0ull; sp[0][1] = 0ull; sp[1][0] = 0ull; sp[1][1] = 0ull;
#pragma unroll 8
        for (int d = 0; d < 32; d++) {
            float2 a = *(const float2*)&Qs[d][tr * 2];
            float4 b = *(const float4*)&Ks[d][sk];
            ull bp0 = pk2(b.x, b.y), bp1 = pk2(b.z, b.w);
            ull ap0 = pk2(a.x, a.x), ap1 = pk2(a.y, a.y);
            fma2(sp[0][0], ap0, bp0); fma2(sp[0][1], ap0, bp1);
            fma2(sp[1][0], ap1, bp0); fma2(sp[1][1], ap1, bp1);
        }
        float s[2][4];
#pragma unroll
        for (int i = 0; i < 2; i++) {
            float2 t0 = upk(sp[i][0]), t1 = upk(sp[i][1]);
            s[i][0] = t0.x; s[i][1] = t0.y; s[i][2] = t1.x; s[i][3] = t1.y;
        }

        // in-register online softmax (per q-row, reduce over 16 lanes = 64 keys)
        float corr[2];
#pragma unroll
        for (int i = 0; i < 2; i++) {
            float mx = fmaxf(fmaxf(s[i][0], s[i][1]), fmaxf(s[i][2], s[i][3]));
            mx = fmaxf(mx, __shfl_xor_sync(0xffffffffu, mx, 1));
            mx = fmaxf(mx, __shfl_xor_sync(0xffffffffu, mx, 2));
            mx = fmaxf(mx, __shfl_xor_sync(0xffffffffu, mx, 4));
            mx = fmaxf(mx, __shfl_xor_sync(0xffffffffu, mx, 8));
            float mnew = fmaxf(m[i], mx);
            float p0 = __expf(s[i][0] - mnew);
            float p1 = __expf(s[i][1] - mnew);
            float p2 = __expf(s[i][2] - mnew);
            float p3 = __expf(s[i][3] - mnew);
            s[i][0] = p0; s[i][1] = p1; s[i][2] = p2; s[i][3] = p3;
            float sum = (p0 + p1) + (p2 + p3);
            sum += __shfl_xor_sync(0xffffffffu, sum, 1);
            sum += __shfl_xor_sync(0xffffffffu, sum, 2);
            sum += __shfl_xor_sync(0xffffffffu, sum, 4);
            sum += __shfl_xor_sync(0xffffffffu, sum, 8);
            float cr = __expf(m[i] - mnew);
            corr[i] = cr;
            l[i] = l[i] * cr + sum;
            m[i] = mnew;
        }
        oacc[0] = mul2(oacc[0], pk2(corr[0], corr[0]));
        oacc[1] = mul2(oacc[1], pk2(corr[1], corr[1]));

        // exchange P through smem (transposed for PV)
#pragma unroll
        for (int j = 0; j < 4; j++)
            *(float2*)&Psh[sk + j][tr * 2] = make_float2(s[0][j], s[1][j]);
        __syncthreads();

        // O += P @ V   (rows 2tr+i, packed d pair tc*2)
#pragma unroll 8
        for (int kj = 0; kj < 64; kj++) {
            float2 p = *(const float2*)&Psh[kj][tr * 2];
            ull vvp = *(const ull*)&Vs[kj][tc * 2];
            fma2(oacc[0], pk2(p.x, p.x), vvp);
            fma2(oacc[1], pk2(p.y, p.y), vvp);
        }
    }
#pragma unroll
    for (int i = 0; i < 2; i++) {
        float inv = 1.f / l[i];
        float2 t = upk(oacc[i]);
        *(float2*)&g_o[(size_t)(q0 + tr * 2 + i) * HV + h * VV + tc * 2] =
            make_float2(t.x * inv, t.y * inv);
    }
}

// ------------------------------- layernorm ------------------------------------
// mean over E, unbiased std (ddof=1), NO eps. One block (256 thr) per row.
__device__ __forceinline__ void ln_core(const float* __restrict__ in,
                                        float* __restrict__ out) {
    __shared__ float reds[8];
    __shared__ float redv[8];
    int r = blockIdx.x, tid = threadIdx.x;
    const float4* x = (const float4*)(in + (size_t)r * EE);
    float4 v = x[tid];
    float s = (v.x + v.y) + (v.z + v.w);
#pragma unroll
    for (int o = 16; o > 0; o >>= 1) s += __shfl_xor_sync(0xffffffffu, s, o);
    if ((tid & 31) == 0) reds[tid >> 5] = s;
    __syncthreads();
    float tot = ((reds[0] + reds[1]) + (reds[2] + reds[3]))
              + ((reds[4] + reds[5]) + (reds[6] + reds[7]));
    float mean = tot * (1.f / 1024.f);
    float dx = v.x - mean, dy = v.y - mean, dz = v.z - mean, dw = v.w - mean;
    float d = (dx * dx + dy * dy) + (dz * dz + dw * dw);
#pragma unroll
    for (int o = 16; o > 0; o >>= 1) d += __shfl_xor_sync(0xffffffffu, d, o);
    if ((tid & 31) == 0) redv[tid >> 5] = d;
    __syncthreads();
    float var = ((redv[0] + redv[1]) + (redv[2] + redv[3]))
              + ((redv[4] + redv[5]) + (redv[6] + redv[7]));
    float rstd = 1.f / sqrtf(var * (1.f / 1023.f));
    float4* o4 = (float4*)(out + (size_t)r * EE);
    o4[tid] = make_float4(dx * rstd, dy * rstd, dz * rstd, dw * rstd);
}

__global__ __launch_bounds__(256) void ln_an_kernel() { ln_core(g_u, g_an); }
__global__ __launch_bounds__(256) void ln_z_kernel() { ln_core(g_u, g_z); }
__global__ __launch_bounds__(256) void ln_out_kernel(float* out) { ln_core(g_u, out); }

// ------------------------------- driver ---------------------------------------
extern "C" void kernel_launch(void* const* d_in, const int* in_sizes, int n_in,
                              void* d_out, int out_size) {
    const int*   context = (const int*)d_in[0];
    const float* table   = (const float*)d_in[1];
    const float* pos     = (const float*)d_in[2];
    const float* Wq      = (const float*)d_in[3];
    const float* Wk      = (const float*)d_in[4];
    const float* Wv      = (const float*)d_in[5];
    const float* Wo      = (const float*)d_in[6];
    const float* W1      = (const float*)d_in[7];
    const float* b1      = (const float*)d_in[8];
    const float* W2      = (const float*)d_in[9];
    const float* b2      = (const float*)d_in[10];
    float* out = (float*)d_out;

    embed_kernel<<<NN, 256>>>(context, table, pos);
    for (int l = 0; l < LL; l++) {
        qkv_x2<<<dim3(NN / 128, HV / 64, 3), 256>>>(Wq, Wk, Wv, l);
        attn_kernel<<<dim3(NN / 32, HH), 256>>>();
        wo_x2<<<dim3(NN / 128, EE / 64), 256>>>(Wo + (size_t)l * HV * EE);
        ln_an_kernel<<<NN, 256>>>();
        ff1_x2<<<dim3(NN / 128, E2 / 64), 256>>>(W1 + (size_t)l * EE * E2,
                                                 b1 + (size_t)l * E2);
        ff2_x2<<<dim3(NN / 128, EE / 64), 256>>>(W2 + (size_t)l * E2 * EE,
                                                 b2 + (size_t)l * EE);
        if (l == LL - 1) ln_out_kernel<<<NN, 256>>>(out);
        else             ln_z_kernel<<<NN, 256>>>();
    }
}